// round 14
// baseline (speedup 1.0000x reference)
#include <cuda_runtime.h>
#include <math.h>

// ROI max pooling, bit-exact vs JAX/XLA reference (contract proven in R2):
//   coords * 0.0625f -> __float2int_rn (round-half-even)
//   bin = roi_size * RN(1/7)   (XLA folds /7 into *recip)
//   floor/ceil edges, clip [0,50], empty bin -> 0.
//
// R14 structure:
//   K1: NCHW->NHWC transpose (32c x 128hw tiles) into g_scr.
//   K2: PERSISTENT flat grid 1184 = 148*8 blocks, 8 blocks/SM forced via
//       launch_bounds -> exactly one wave; each block loops over (m, ph)
//       work units (1792 total, so blocks take 1-2 units; balanced, no
//       half-empty second wave). Unit body = R13 champion: one bin/warp,
//       256 ch (2x float4/lane), span_w-specialized static load batches,
//       smem-staged ordered epilogue (R8: scattered STGs serialize LTS).

static constexpr int   kC    = 256;
static constexpr int   kH    = 50;
static constexpr int   kW    = 50;
static constexpr int   kHW   = kH * kW;        // 2500
static constexpr int   kBins = 49;
static constexpr float kScale = 0.0625f;
static constexpr int   kPersistBlocks = 148 * 8;   // one full wave

__device__ float g_scr[4 * kHW * kC];          // 10.24 MB channels-last scratch

// ---------------- K1: NCHW -> NHWC transpose, 32c x 128hw tile
__global__ void __launch_bounds__(256)
transpose_kernel(const float* __restrict__ x)
{
    __shared__ float tile[32][133];
    const int b   = blockIdx.z;
    const int hw0 = blockIdx.x * 128;
    const int c0  = blockIdx.y * 32;
    const int t   = threadIdx.x;

    {
        const int q = t & 7;
        const int c = t >> 3;
        const float* src = x + ((size_t)b * kC + c0 + c) * kHW;
        #pragma unroll
        for (int k = 0; k < 4; ++k) {
            const int hwl = 4 * (q + 8 * k);
            const int hw  = hw0 + hwl;
            if (hw + 3 < kHW) {
                const float4 f = *(const float4*)(src + hw);
                tile[c][hwl + 0] = f.x;
                tile[c][hwl + 1] = f.y;
                tile[c][hwl + 2] = f.z;
                tile[c][hwl + 3] = f.w;
            } else {
                for (int e = 0; e < 4; ++e)
                    if (hw + e < kHW) tile[c][hwl + e] = src[hw + e];
            }
        }
    }
    __syncthreads();
    {
        const int cq = t & 7;
        #pragma unroll
        for (int k = 0; k < 4; ++k) {
            const int hwi = (t >> 3) + 32 * k;
            const int hw  = hw0 + hwi;
            if (hw < kHW) {
                float4 f;
                f.x = tile[4 * cq + 0][hwi];
                f.y = tile[4 * cq + 1][hwi];
                f.z = tile[4 * cq + 2][hwi];
                f.w = tile[4 * cq + 3][hwi];
                *(float4*)(g_scr + ((size_t)b * kHW + hw) * kC + c0 + 4 * cq) = f;
            }
        }
    }
}

// ---------------- K2: persistent, one (m, ph) unit per loop iteration
__global__ void __launch_bounds__(224, 8)
roi_pool_nhwc(const float* __restrict__ rois,
              float* __restrict__ out,
              int nunits)
{
    __shared__ __align__(16) float sout[kC * 7];       // 7168 B

    const int t    = threadIdx.x;
    const int lane = t & 31;
    const int pw   = t >> 5;                   // warp id = bin column 0..6

    for (int unit = blockIdx.x; unit < nunits; unit += kPersistBlocks) {
        const int m  = unit / 7;
        const int ph = unit - m * 7;

        const float* r = rois + (size_t)m * 5;

        // Uniform per-warp bin bounds.
        const int b  = (int)r[0];
        const int x1 = __float2int_rn(r[1] * kScale);
        const int y1 = __float2int_rn(r[2] * kScale);
        const int x2 = __float2int_rn(r[3] * kScale);
        const int y2 = __float2int_rn(r[4] * kScale);

        const float roi_h = (float)max(y2 - y1 + 1, 1);
        const float roi_w = (float)max(x2 - x1 + 1, 1);
        const float kInv7 = 1.0f / 7.0f;       // RN(1/7), matches XLA
        const float bh = roi_h * kInv7;
        const float bw = roi_w * kInv7;

        const int hs = min(max((int)floorf((float)ph * bh)       + y1, 0), kH);
        const int he = min(max((int)ceilf((float)(ph + 1) * bh)  + y1, 0), kH);
        const int ws = min(max((int)floorf((float)pw * bw)       + x1, 0), kW);
        const int we = min(max((int)ceilf((float)(pw + 1) * bw)  + x1, 0), kW);

        const float4* __restrict__ base4 =
            (const float4*)g_scr + (size_t)b * (kHW * kC / 4) + lane;

        float v0 = -INFINITY, v1 = -INFINITY, v2 = -INFINITY, v3 = -INFINITY;
        float u0 = -INFINITY, u1 = -INFINITY, u2 = -INFINITY, u3 = -INFINITY;

        const int span_w = we - ws;
        if (span_w == 1) {
            #pragma unroll 2
            for (int h = hs; h < he; ++h) {
                const float4* __restrict__ p = base4 + (size_t)(h * kW + ws) * 64;
                const float4 f = __ldg(p);
                const float4 g = __ldg(p + 32);
                v0 = fmaxf(v0, f.x); v1 = fmaxf(v1, f.y);
                v2 = fmaxf(v2, f.z); v3 = fmaxf(v3, f.w);
                u0 = fmaxf(u0, g.x); u1 = fmaxf(u1, g.y);
                u2 = fmaxf(u2, g.z); u3 = fmaxf(u3, g.w);
            }
        } else if (span_w == 2) {
            #pragma unroll 2
            for (int h = hs; h < he; ++h) {
                const float4* __restrict__ p = base4 + (size_t)(h * kW + ws) * 64;
                const float4 f0 = __ldg(p);
                const float4 g0 = __ldg(p + 32);
                const float4 f1 = __ldg(p + 64);
                const float4 g1 = __ldg(p + 96);
                v0 = fmaxf(fmaxf(v0, f0.x), f1.x);
                v1 = fmaxf(fmaxf(v1, f0.y), f1.y);
                v2 = fmaxf(fmaxf(v2, f0.z), f1.z);
                v3 = fmaxf(fmaxf(v3, f0.w), f1.w);
                u0 = fmaxf(fmaxf(u0, g0.x), g1.x);
                u1 = fmaxf(fmaxf(u1, g0.y), g1.y);
                u2 = fmaxf(fmaxf(u2, g0.z), g1.z);
                u3 = fmaxf(fmaxf(u3, g0.w), g1.w);
            }
        } else if (span_w > 2) {
            for (int h = hs; h < he; ++h) {
                const float4* __restrict__ p = base4 + (size_t)(h * kW + ws) * 64;
                #pragma unroll 2
                for (int w = ws; w < we; ++w) {
                    const float4 f = __ldg(p);
                    const float4 g = __ldg(p + 32);
                    v0 = fmaxf(v0, f.x); v1 = fmaxf(v1, f.y);
                    v2 = fmaxf(v2, f.z); v3 = fmaxf(v3, f.w);
                    u0 = fmaxf(u0, g.x); u1 = fmaxf(u1, g.y);
                    u2 = fmaxf(u2, g.z); u3 = fmaxf(u3, g.w);
                    p += 64;
                }
            }
        }

        const bool valid = (he > hs) && (we > ws);
        float* s = sout + (4 * lane) * 7 + pw;      // c-major staging
        s[0 * 7] = valid ? v0 : 0.0f;
        s[1 * 7] = valid ? v1 : 0.0f;
        s[2 * 7] = valid ? v2 : 0.0f;
        s[3 * 7] = valid ? v3 : 0.0f;
        float* s2 = s + 128 * 7;
        s2[0 * 7] = valid ? u0 : 0.0f;
        s2[1 * 7] = valid ? u1 : 0.0f;
        s2[2 * 7] = valid ? u2 : 0.0f;
        s2[3 * 7] = valid ? u3 : 0.0f;
        __syncthreads();

        // Ordered copy of this unit's out slice: {m, c, ph, j}.
        float* __restrict__ obase = out + (size_t)m * (kC * kBins) + ph * 7;
        #pragma unroll
        for (int k = t; k < kC * 7; k += 224) {     // 8 iterations
            const int c = k / 7;
            const int j = k - c * 7;
            obase[c * kBins + j] = sout[k];
        }
        __syncthreads();                            // sout reuse barrier
    }
}

extern "C" void kernel_launch(void* const* d_in, const int* in_sizes, int n_in,
                              void* d_out, int out_size)
{
    const float* x    = (const float*)d_in[0];
    const float* rois = (const float*)d_in[1];
    float*       out  = (float*)d_out;

    const int B = in_sizes[0] / (kC * kHW);
    const int M = in_sizes[1] / 5;

    dim3 tgrid((kHW + 127) / 128, kC / 32, B); // (20, 8, B) = 640 blocks
    transpose_kernel<<<tgrid, 256>>>(x);

    roi_pool_nhwc<<<kPersistBlocks, 224>>>(rois, out, M * 7);
}

// round 15
// speedup vs baseline: 1.1233x; 1.1233x over previous
#include <cuda_runtime.h>
#include <math.h>

// ROI max pooling, bit-exact vs JAX/XLA reference (contract proven in R2):
//   coords * 0.0625f -> __float2int_rn (round-half-even)
//   bin = roi_size * RN(1/7)   (XLA folds /7 into *recip)
//   floor/ceil edges, clip [0,50], empty bin -> 0.
//
// R15 structure:
//   K1: NCHW->NHWC transpose (32c x 128hw tiles) into g_scr.
//   K2: grid (M,7) x 224thr, one bin/warp over 256 ch (R13 champion body),
//       launched with PROGRAMMATIC DEPENDENT LAUNCH: decode overlaps K1's
//       tail, cudaGridDependencySynchronize() guards the g_scr gather.
//       Epilogue rewritten: div/mod once, linear LDS, strided STG.

static constexpr int   kC    = 256;
static constexpr int   kH    = 50;
static constexpr int   kW    = 50;
static constexpr int   kHW   = kH * kW;        // 2500
static constexpr int   kBins = 49;
static constexpr float kScale = 0.0625f;

__device__ float g_scr[4 * kHW * kC];          // 10.24 MB channels-last scratch

// ---------------- K1: NCHW -> NHWC transpose, 32c x 128hw tile
__global__ void __launch_bounds__(256)
transpose_kernel(const float* __restrict__ x)
{
    __shared__ float tile[32][133];
    const int b   = blockIdx.z;
    const int hw0 = blockIdx.x * 128;
    const int c0  = blockIdx.y * 32;
    const int t   = threadIdx.x;

    {
        const int q = t & 7;
        const int c = t >> 3;
        const float* src = x + ((size_t)b * kC + c0 + c) * kHW;
        #pragma unroll
        for (int k = 0; k < 4; ++k) {
            const int hwl = 4 * (q + 8 * k);
            const int hw  = hw0 + hwl;
            if (hw + 3 < kHW) {
                const float4 f = *(const float4*)(src + hw);
                tile[c][hwl + 0] = f.x;
                tile[c][hwl + 1] = f.y;
                tile[c][hwl + 2] = f.z;
                tile[c][hwl + 3] = f.w;
            } else {
                for (int e = 0; e < 4; ++e)
                    if (hw + e < kHW) tile[c][hwl + e] = src[hw + e];
            }
        }
    }
    __syncthreads();
    {
        const int cq = t & 7;
        #pragma unroll
        for (int k = 0; k < 4; ++k) {
            const int hwi = (t >> 3) + 32 * k;
            const int hw  = hw0 + hwi;
            if (hw < kHW) {
                float4 f;
                f.x = tile[4 * cq + 0][hwi];
                f.y = tile[4 * cq + 1][hwi];
                f.z = tile[4 * cq + 2][hwi];
                f.w = tile[4 * cq + 3][hwi];
                *(float4*)(g_scr + ((size_t)b * kHW + hw) * kC + c0 + 4 * cq) = f;
            }
        }
    }
}

// ---------------- K2: one bin per warp, 256 channels per warp (PDL consumer)
__global__ void __launch_bounds__(224)
roi_pool_nhwc(const float* __restrict__ rois,
              float* __restrict__ out)
{
    __shared__ __align__(16) float sout[kC * 7];       // 7168 B

    const int m    = blockIdx.x;               // ROI
    const int ph   = blockIdx.y;               // 0..6
    const int t    = threadIdx.x;
    const int lane = t & 31;
    const int pw   = t >> 5;                   // warp id = bin column 0..6

    // ---- Decode phase: touches only rois; runs concurrently with K1 tail.
    const float* r = rois + (size_t)m * 5;
    const int b  = (int)r[0];
    const int x1 = __float2int_rn(r[1] * kScale);
    const int y1 = __float2int_rn(r[2] * kScale);
    const int x2 = __float2int_rn(r[3] * kScale);
    const int y2 = __float2int_rn(r[4] * kScale);

    const float roi_h = (float)max(y2 - y1 + 1, 1);
    const float roi_w = (float)max(x2 - x1 + 1, 1);
    const float kInv7 = 1.0f / 7.0f;           // RN(1/7), matches XLA
    const float bh = roi_h * kInv7;
    const float bw = roi_w * kInv7;

    const int hs = min(max((int)floorf((float)ph * bh)       + y1, 0), kH);
    const int he = min(max((int)ceilf((float)(ph + 1) * bh)  + y1, 0), kH);
    const int ws = min(max((int)floorf((float)pw * bw)       + x1, 0), kW);
    const int we = min(max((int)ceilf((float)(pw + 1) * bw)  + x1, 0), kW);

    // Epilogue indices (computed early, cheap): t = 32*? no: tc = t/7, tj = t%7
    const int tc = t / 7;
    const int tj = t - tc * 7;

    // ---- Wait for K1 (transpose) results before reading g_scr.
    cudaGridDependencySynchronize();

    const float4* __restrict__ base4 =
        (const float4*)g_scr + (size_t)b * (kHW * kC / 4) + lane;

    float v0 = -INFINITY, v1 = -INFINITY, v2 = -INFINITY, v3 = -INFINITY;
    float u0 = -INFINITY, u1 = -INFINITY, u2 = -INFINITY, u3 = -INFINITY;

    const int span_w = we - ws;
    if (span_w == 1) {
        #pragma unroll 2
        for (int h = hs; h < he; ++h) {
            const float4* __restrict__ p = base4 + (size_t)(h * kW + ws) * 64;
            const float4 f = __ldg(p);
            const float4 g = __ldg(p + 32);
            v0 = fmaxf(v0, f.x); v1 = fmaxf(v1, f.y);
            v2 = fmaxf(v2, f.z); v3 = fmaxf(v3, f.w);
            u0 = fmaxf(u0, g.x); u1 = fmaxf(u1, g.y);
            u2 = fmaxf(u2, g.z); u3 = fmaxf(u3, g.w);
        }
    } else if (span_w == 2) {
        #pragma unroll 2
        for (int h = hs; h < he; ++h) {
            const float4* __restrict__ p = base4 + (size_t)(h * kW + ws) * 64;
            const float4 f0 = __ldg(p);
            const float4 g0 = __ldg(p + 32);
            const float4 f1 = __ldg(p + 64);
            const float4 g1 = __ldg(p + 96);
            v0 = fmaxf(fmaxf(v0, f0.x), f1.x);
            v1 = fmaxf(fmaxf(v1, f0.y), f1.y);
            v2 = fmaxf(fmaxf(v2, f0.z), f1.z);
            v3 = fmaxf(fmaxf(v3, f0.w), f1.w);
            u0 = fmaxf(fmaxf(u0, g0.x), g1.x);
            u1 = fmaxf(fmaxf(u1, g0.y), g1.y);
            u2 = fmaxf(fmaxf(u2, g0.z), g1.z);
            u3 = fmaxf(fmaxf(u3, g0.w), g1.w);
        }
    } else if (span_w > 2) {
        for (int h = hs; h < he; ++h) {
            const float4* __restrict__ p = base4 + (size_t)(h * kW + ws) * 64;
            #pragma unroll 2
            for (int w = ws; w < we; ++w) {
                const float4 f = __ldg(p);
                const float4 g = __ldg(p + 32);
                v0 = fmaxf(v0, f.x); v1 = fmaxf(v1, f.y);
                v2 = fmaxf(v2, f.z); v3 = fmaxf(v3, f.w);
                u0 = fmaxf(u0, g.x); u1 = fmaxf(u1, g.y);
                u2 = fmaxf(u2, g.z); u3 = fmaxf(u3, g.w);
                p += 64;
            }
        }
    }

    const bool valid = (he > hs) && (we > ws);
    float* s = sout + (4 * lane) * 7 + pw;      // c-major staging
    s[0 * 7] = valid ? v0 : 0.0f;
    s[1 * 7] = valid ? v1 : 0.0f;
    s[2 * 7] = valid ? v2 : 0.0f;
    s[3 * 7] = valid ? v3 : 0.0f;
    float* s2 = s + 128 * 7;
    s2[0 * 7] = valid ? u0 : 0.0f;
    s2[1 * 7] = valid ? u1 : 0.0f;
    s2[2 * 7] = valid ? u2 : 0.0f;
    s2[3 * 7] = valid ? u3 : 0.0f;
    __syncthreads();

    // Epilogue: linear smem reads (sout[t + 224*it]), strided global stores.
    // element k = c*7 + j  ->  out index c*49 + ph*7 + j, c = tc + 32*it.
    {
        float* __restrict__ o =
            out + (size_t)m * (kC * kBins) + (size_t)tc * kBins + ph * 7 + tj;
        const float* __restrict__ sp = sout + t;
        #pragma unroll
        for (int it = 0; it < 8; ++it) {        // 8*224 = 1792 = 256*7
            o[(size_t)(32 * it) * kBins] = sp[224 * it];
        }
    }
}

extern "C" void kernel_launch(void* const* d_in, const int* in_sizes, int n_in,
                              void* d_out, int out_size)
{
    const float* x    = (const float*)d_in[0];
    const float* rois = (const float*)d_in[1];
    float*       out  = (float*)d_out;

    const int B = in_sizes[0] / (kC * kHW);
    const int M = in_sizes[1] / 5;

    dim3 tgrid((kHW + 127) / 128, kC / 32, B); // (20, 8, B) = 640 blocks
    transpose_kernel<<<tgrid, 256>>>(x);

    // K2 with programmatic dependent launch: overlaps decode with K1 tail.
    cudaLaunchConfig_t cfg = {};
    cfg.gridDim  = dim3((unsigned)M, 7, 1);
    cfg.blockDim = dim3(224, 1, 1);
    cfg.dynamicSmemBytes = 0;
    cfg.stream = 0;
    cudaLaunchAttribute attrs[1];
    attrs[0].id = cudaLaunchAttributeProgrammaticStreamSerialization;
    attrs[0].val.programmaticStreamSerializationAllowed = 1;
    cfg.attrs = attrs;
    cfg.numAttrs = 1;
    cudaLaunchKernelEx(&cfg, roi_pool_nhwc, rois, out);
}